// round 15
// baseline (speedup 1.0000x reference)
#include <cuda_runtime.h>
#include <cuda_bf16.h>
#include <cuda_fp16.h>
#include <cstdint>

// ---------------------------------------------------------------------------
// Problem constants: N=50000, E=800000, F=256
// ---------------------------------------------------------------------------
#define NMAX 50176   // 50000 rounded up to multiple of 128
#define EMAX 800000

// Scratch (device globals; allocation-free kernel_launch)
__device__ float g_dinv[NMAX];
__device__ int   g_indeg[NMAX];
__device__ int   g_rowptr[NMAX + 1];
__device__ int   g_cursor[NMAX];
__device__ int   g_bsum[64];
__device__ int   g_eidx[EMAX];
__device__ float g_h1s [(size_t)NMAX * 128];          // x@W1 (unscaled)
__device__ float g_h2s [(size_t)NMAX * 12];           // dinv * (out1@W2)
__device__ float g_h2  [(size_t)NMAX * 12];           // out2
__device__ __half g_m1h[(size_t)NMAX * 512];          // fp16 m1 (rows>=N stay 0)
__device__ __nv_bfloat16 g_w1th[128 * 256];           // bf16 split of W1^T
__device__ __nv_bfloat16 g_w1tl[128 * 256];
__device__ __half g_bth[512 * 512];                   // fp16 split of L2^T
__device__ __half g_btl[512 * 512];

// ---------------------------------------------------------------------------
// Streams/events for fork-join overlap (static-init; fallback to stream 0)
// ---------------------------------------------------------------------------
struct StreamInit {
    cudaStream_t s2 = nullptr;
    cudaEvent_t evF = nullptr, evC = nullptr, evP = nullptr;
    bool ok = false;
    StreamInit() {
        ok = (cudaStreamCreateWithFlags(&s2, cudaStreamNonBlocking) == cudaSuccess)
          && (cudaEventCreateWithFlags(&evF, cudaEventDisableTiming) == cudaSuccess)
          && (cudaEventCreateWithFlags(&evC, cudaEventDisableTiming) == cudaSuccess)
          && (cudaEventCreateWithFlags(&evP, cudaEventDisableTiming) == cudaSuccess);
    }
};
static StreamInit g_si;

// ---------------------------------------------------------------------------
// PTX helpers
// ---------------------------------------------------------------------------
__device__ __forceinline__ uint32_t smem_u32(const void* p) {
    return (uint32_t)__cvta_generic_to_shared(p);
}
__device__ __forceinline__ void ldm_x4(uint32_t* r, uint32_t addr) {
    asm volatile("ldmatrix.sync.aligned.m8n8.x4.shared.b16 {%0,%1,%2,%3}, [%4];"
                 : "=r"(r[0]), "=r"(r[1]), "=r"(r[2]), "=r"(r[3]) : "r"(addr));
}
__device__ __forceinline__ void mma_bf16(float* c, const uint32_t* a,
                                         uint32_t b0, uint32_t b1) {
    asm volatile(
        "mma.sync.aligned.m16n8k16.row.col.f32.bf16.bf16.f32 "
        "{%0,%1,%2,%3}, {%4,%5,%6,%7}, {%8,%9}, {%0,%1,%2,%3};"
        : "+f"(c[0]), "+f"(c[1]), "+f"(c[2]), "+f"(c[3])
        : "r"(a[0]), "r"(a[1]), "r"(a[2]), "r"(a[3]), "r"(b0), "r"(b1));
}
__device__ __forceinline__ void mma_f16(float* c, const uint32_t* a,
                                        uint32_t b0, uint32_t b1) {
    asm volatile(
        "mma.sync.aligned.m16n8k16.row.col.f32.f16.f16.f32 "
        "{%0,%1,%2,%3}, {%4,%5,%6,%7}, {%8,%9}, {%0,%1,%2,%3};"
        : "+f"(c[0]), "+f"(c[1]), "+f"(c[2]), "+f"(c[3])
        : "r"(a[0]), "r"(a[1]), "r"(a[2]), "r"(a[3]), "r"(b0), "r"(b1));
}
#define CP_ASYNC16(dst, src) \
    asm volatile("cp.async.cg.shared.global [%0], [%1], 16;" :: "r"(dst), "l"(src))
#define CP_COMMIT() asm volatile("cp.async.commit_group;" ::: "memory")
#define CP_WAIT1()  asm volatile("cp.async.wait_group 1;" ::: "memory")

__device__ __forceinline__ uint32_t pk_bf2(__nv_bfloat16 a, __nv_bfloat16 b) {
    __nv_bfloat162 t(a, b);
    return *reinterpret_cast<uint32_t*>(&t);
}
__device__ __forceinline__ uint32_t pk_h2(__half a, __half b) {
    __half2 t = __halves2half2(a, b);
    return *reinterpret_cast<uint32_t*>(&t);
}

// ---------------------------------------------------------------------------
// Degree / dinv / CSR build (hierarchical scan)
// ---------------------------------------------------------------------------
__global__ void k_ideg_init() {
    int i = blockIdx.x * blockDim.x + threadIdx.x;
    if (i < NMAX) g_indeg[i] = 0;
}
__global__ void k_ideg_edges(const int* __restrict__ col, int E) {
    int e = blockIdx.x * blockDim.x + threadIdx.x;
    if (e < E) atomicAdd(&g_indeg[col[e]], 1);
}
__global__ void k_dinv_calc() {
    int i = blockIdx.x * blockDim.x + threadIdx.x;
    if (i < NMAX) g_dinv[i] = rsqrtf((float)(g_indeg[i] + 1));
}
__global__ void __launch_bounds__(1024) k_scan1(int n) {
    __shared__ int wsum[32];
    const int tid = threadIdx.x, lane = tid & 31, wid = tid >> 5;
    int i = blockIdx.x * 1024 + tid;
    int v = (i < n) ? g_indeg[i] : 0;
    int s = v;
#pragma unroll
    for (int o = 1; o < 32; o <<= 1) {
        int t = __shfl_up_sync(0xffffffffu, s, o);
        if (lane >= o) s += t;
    }
    if (lane == 31) wsum[wid] = s;
    __syncthreads();
    if (wid == 0) {
        int w = wsum[lane];
#pragma unroll
        for (int o = 1; o < 32; o <<= 1) {
            int t = __shfl_up_sync(0xffffffffu, w, o);
            if (lane >= o) w += t;
        }
        wsum[lane] = w;
    }
    __syncthreads();
    int excl = s - v + (wid ? wsum[wid - 1] : 0);
    if (i < n) g_rowptr[i] = excl;
    if (tid == 1023) g_bsum[blockIdx.x] = wsum[31];
}
__global__ void k_scan2(int nb, int n) {
    int acc = 0;
    for (int b = 0; b < nb; b++) { int t = g_bsum[b]; g_bsum[b] = acc; acc += t; }
    g_rowptr[n] = acc;
}
__global__ void k_scan3(int n) {
    int i = blockIdx.x * blockDim.x + threadIdx.x;
    if (i < n) {
        int v = g_rowptr[i] + g_bsum[i >> 10];
        g_rowptr[i] = v;
        g_cursor[i] = v;
    }
}
__global__ void k_fill(const int* __restrict__ row,
                       const int* __restrict__ col, int E) {
    int e = blockIdx.x * blockDim.x + threadIdx.x;
    if (e >= E) return;
    int p = atomicAdd(&g_cursor[col[e]], 1);
    g_eidx[p] = row[e];
}

// ---------------------------------------------------------------------------
// Transposed-weight prep + output init
// ---------------------------------------------------------------------------
__global__ void k_bt_prep(const float* __restrict__ W,
                          __nv_bfloat16* __restrict__ th,
                          __nv_bfloat16* __restrict__ tl, int K, int N) {
    int i = blockIdx.x * blockDim.x + threadIdx.x;
    if (i >= N * K) return;
    int n = i / K, k = i - n * K;
    float v = W[(size_t)k * N + n];
    __nv_bfloat16 h = __float2bfloat16(v);
    th[i] = h;
    tl[i] = __float2bfloat16(v - __bfloat162float(h));
}
__global__ void k_bt_prep_h(const float* __restrict__ W,
                            __half* __restrict__ th,
                            __half* __restrict__ tl, int K, int N) {
    int i = blockIdx.x * blockDim.x + threadIdx.x;
    if (i >= N * K) return;
    int n = i / K, k = i - n * K;
    float v = W[(size_t)k * N + n];
    __half h = __float2half(v);
    th[i] = h;
    tl[i] = __float2half(v - __half2float(h));
}
__global__ void k_out_init(const float* __restrict__ lb3,
                           float* __restrict__ out, int n) {
    int i = blockIdx.x * blockDim.x + threadIdx.x;
    if (i < n) ((float2*)out)[i] = make_float2(lb3[0], lb3[1]);
}

// ---------------------------------------------------------------------------
// Layer-1 GEMM, fused x-split (bf16 3-term): C[m,n] = x[m,:] @ W1 (unscaled).
// ---------------------------------------------------------------------------
#define SMP 40
#define MAT_B (128 * SMP * 2)    // 10240 B per 128x32 16-bit matrix
#define A1_AH (4 * MAT_B)
#define A1_AL (A1_AH + MAT_B)
#define DSM_1F (A1_AH + 2 * MAT_B)

__global__ void __launch_bounds__(256) k_mma1f(
    const float* __restrict__ x,
    const __nv_bfloat16* __restrict__ BTh, const __nv_bfloat16* __restrict__ BTl,
    float* __restrict__ C, int Nreal)
{
    extern __shared__ char dsm[];
    const uint32_t sb = smem_u32(dsm);
    const int tid = threadIdx.x;
    const int lane = tid & 31;
    const int wid = tid >> 5;
    const int wm = (wid & 3) * 32;
    const int wn = (wid >> 2) * 64;
    const int m0 = blockIdx.x * 128;
    const int K = 256, ntiles = 8, N = 128;

    float acc[2][8][4];
#pragma unroll
    for (int i = 0; i < 2; i++)
#pragma unroll
        for (int j = 0; j < 8; j++)
#pragma unroll
            for (int t = 0; t < 4; t++) acc[i][j][t] = 0.f;

    const int a_lr = lane & 15, a_lc = (lane >> 4) * 8;
    const int b_lr = (lane & 7) + ((lane >> 4) << 3);
    const int b_lc = ((lane >> 3) & 1) * 8;

    auto issueB = [&](int kt, int buf) {
#pragma unroll
        for (int s = tid; s < 512; s += 256) {
            int row = s >> 2, q = s & 3;
            uint32_t so = sb + buf * (2 * MAT_B)
                        + (uint32_t)(row * SMP + q * 8) * 2;
            size_t gb = (size_t)row * K + kt * 32 + q * 8;
            CP_ASYNC16(so,         BTh + gb);
            CP_ASYNC16(so + MAT_B, BTl + gb);
        }
    };

    issueB(0, 0);
    CP_COMMIT();

    const int arow = tid >> 1;
    const int ch = (tid & 1) * 16;
    int gr = m0 + arow;
    if (gr >= Nreal) gr = Nreal - 1;
    const float* xrow = x + (size_t)gr * 256;

    for (int kt = 0; kt < ntiles; kt++) {
        const int cur = kt & 1;
        __syncthreads();
        if (kt + 1 < ntiles) issueB(kt + 1, cur ^ 1);
        CP_COMMIT();

#pragma unroll
        for (int q = 0; q < 4; q++) {
            int col = ch + q * 4;
            float4 s = *(const float4*)(xrow + kt * 32 + col);
            __nv_bfloat16 h0 = __float2bfloat16(s.x);
            __nv_bfloat16 h1 = __float2bfloat16(s.y);
            __nv_bfloat16 h2 = __float2bfloat16(s.z);
            __nv_bfloat16 h3 = __float2bfloat16(s.w);
            uint2 hi = make_uint2(pk_bf2(h0, h1), pk_bf2(h2, h3));
            float l0 = s.x - __bfloat162float(h0);
            float l1 = s.y - __bfloat162float(h1);
            float l2 = s.z - __bfloat162float(h2);
            float l3 = s.w - __bfloat162float(h3);
            uint2 lo = make_uint2(
                pk_bf2(__float2bfloat16(l0), __float2bfloat16(l1)),
                pk_bf2(__float2bfloat16(l2), __float2bfloat16(l3)));
            uint32_t off = (uint32_t)(arow * SMP + col) * 2;
            *(uint2*)(dsm + A1_AH + off) = hi;
            *(uint2*)(dsm + A1_AL + off) = lo;
        }

        CP_WAIT1();
        __syncthreads();

        const uint32_t bA = sb + A1_AH;
        const uint32_t bB = sb + cur * (2 * MAT_B);
#pragma unroll
        for (int ks = 0; ks < 2; ks++) {
            uint32_t ah[2][4], al[2][4], bh[4][4], bl[4][4];
#pragma unroll
            for (int mt = 0; mt < 2; mt++) {
                uint32_t off = (uint32_t)((wm + mt * 16 + a_lr) * SMP
                                          + ks * 16 + a_lc) * 2;
                ldm_x4(ah[mt], bA + off);
                ldm_x4(al[mt], bA + MAT_B + off);
            }
#pragma unroll
            for (int p = 0; p < 4; p++) {
                uint32_t off = (uint32_t)((wn + p * 16 + b_lr) * SMP
                                          + ks * 16 + b_lc) * 2;
                ldm_x4(bh[p], bB + off);
                ldm_x4(bl[p], bB + MAT_B + off);
            }
#pragma unroll
            for (int mt = 0; mt < 2; mt++)
#pragma unroll
                for (int nt = 0; nt < 8; nt++) {
                    int p = nt >> 1, h = (nt & 1) * 2;
                    mma_bf16(acc[mt][nt], ah[mt], bh[p][h], bh[p][h + 1]);
                    mma_bf16(acc[mt][nt], ah[mt], bl[p][h], bl[p][h + 1]);
                    mma_bf16(acc[mt][nt], al[mt], bh[p][h], bh[p][h + 1]);
                }
        }
    }

#pragma unroll
    for (int mt = 0; mt < 2; mt++) {
#pragma unroll
        for (int r = 0; r < 2; r++) {
            int m = m0 + wm + mt * 16 + (lane >> 2) + r * 8;
#pragma unroll
            for (int nt = 0; nt < 8; nt++) {
                int n = wn + nt * 8 + (lane & 3) * 2;
                *(float2*)(C + (size_t)m * N + n)
                    = make_float2(acc[mt][nt][r * 2 + 0],
                                  acc[mt][nt][r * 2 + 1]);
            }
        }
    }
}

// ---------------------------------------------------------------------------
// m1h[N,512] = fp16(relu(h2@L1 + lb1)). Rows >= n stay 0 (never written).
// ---------------------------------------------------------------------------
__global__ void __launch_bounds__(256) k_mlp1h(
    const float* __restrict__ L1, const float* __restrict__ lb1, int n) {
    __shared__ float sL[12 * 512];
    __shared__ float sb[512];
    __shared__ float sh[64 * 12];
    int node0 = blockIdx.x * 64;
    for (int i = threadIdx.x; i < 12 * 512; i += 256) sL[i] = L1[i];
    for (int i = threadIdx.x; i < 512; i += 256) sb[i] = lb1[i];
    for (int i = threadIdx.x; i < 64 * 12; i += 256) {
        int nn = node0 + i / 12;
        sh[i] = (nn < n) ? g_h2[(size_t)node0 * 12 + i] : 0.f;
    }
    __syncthreads();
    for (int idx = threadIdx.x; idx < 64 * 256; idx += 256) {
        int ln = idx >> 8;
        int j = (idx & 255) * 2;
        int node = node0 + ln;
        if (node >= n) continue;
        float s0 = sb[j], s1 = sb[j + 1];
#pragma unroll
        for (int k = 0; k < 12; k++) {
            float h = sh[ln * 12 + k];
            s0 += h * sL[k * 512 + j];
            s1 += h * sL[k * 512 + j + 1];
        }
        s0 = fmaxf(s0, 0.f);
        s1 = fmaxf(s1, 0.f);
        *(uint32_t*)(g_m1h + (size_t)node * 512 + j)
            = pk_h2(__float2half(s0), __float2half(s1));
    }
}

// ---------------------------------------------------------------------------
// MLP GEMM, fp16 2-term B-split, 3-stage cp.async pipeline:
//   out[m,:2] += L3^T @ relu( A@(Bh+Bl) + lb2 ),  A = g_m1h
// Grid (Ntiles=4, Mtiles=392): n-tile on x => A m-tile L2-resident.
// ---------------------------------------------------------------------------
#define G_STG (3 * MAT_B)                      // A,Bh,Bl per stage: 30720
#define G_L3  (3 * G_STG)                      // 92160
#define DSM_G (G_L3 + 128 * 2 * 4)             // 93184

__global__ void __launch_bounds__(256) k_mma2f(
    const __half* __restrict__ Ah,
    const __half* __restrict__ BTh, const __half* __restrict__ BTl,
    const float* __restrict__ lb2,
    const float* __restrict__ L3, float* __restrict__ outp, int Mreal)
{
    extern __shared__ char dsm[];
    const uint32_t sb = smem_u32(dsm);
    float* sL3 = (float*)(dsm + G_L3);

    const int tid = threadIdx.x;
    const int lane = tid & 31;
    const int wid = tid >> 5;
    const int wm = (wid & 3) * 32;
    const int wn = (wid >> 2) * 64;
    const int m0 = blockIdx.y * 128;
    const int n0 = blockIdx.x * 128;
    const int K = 512, ntiles = 16;

    if (tid < 128) ((float2*)sL3)[tid] = ((const float2*)L3)[n0 + tid];

    float acc[2][8][4];
#pragma unroll
    for (int i = 0; i < 2; i++)
#pragma unroll
        for (int j = 0; j < 8; j++)
#pragma unroll
            for (int t = 0; t < 4; t++) acc[i][j][t] = 0.f;

    const int a_lr = lane & 15, a_lc = (lane >> 4) * 8;
    const int b_lr = (lane & 7) + ((lane >> 4) << 3);
    const int b_lc = ((lane >> 3) & 1) * 8;

    auto issue = [&](int kt, int buf) {
        const uint32_t bb = sb + buf * G_STG;
#pragma unroll
        for (int s = tid; s < 512; s += 256) {
            int row = s >> 2, q = s & 3;
            uint32_t so = (uint32_t)(row * SMP + q * 8) * 2;
            size_t ga = (size_t)(m0 + row) * K + kt * 32 + q * 8;
            size_t gb = (size_t)(n0 + row) * K + kt * 32 + q * 8;
            CP_ASYNC16(bb + so,             Ah + ga);
            CP_ASYNC16(bb + MAT_B + so,     BTh + gb);
            CP_ASYNC16(bb + 2 * MAT_B + so, BTl + gb);
        }
    };

    issue(0, 0); CP_COMMIT();
    issue(1, 1); CP_COMMIT();

    int cur = 0;
    for (int kt = 0; kt < ntiles; kt++) {
        CP_WAIT1();                 // group kt landed (kt+1 may be in flight)
        __syncthreads();            // all warps done with buffer being refilled
        if (kt + 2 < ntiles) issue(kt + 2, (cur + 2 >= 3) ? cur - 1 : cur + 2);
        CP_COMMIT();

        const uint32_t bA = sb + cur * G_STG;
        const uint32_t bB = bA + MAT_B;
#pragma unroll
        for (int ks = 0; ks < 2; ks++) {
            uint32_t ah[2][4], bh[4][4], bl[4][4];
#pragma unroll
            for (int mt = 0; mt < 2; mt++) {
                uint32_t off = (uint32_t)((wm + mt * 16 + a_lr) * SMP
                                          + ks * 16 + a_lc) * 2;
                ldm_x4(ah[mt], bA + off);
            }
#pragma unroll
            for (int p = 0; p < 4; p++) {
                uint32_t off = (uint32_t)((wn + p * 16 + b_lr) * SMP
                                          + ks * 16 + b_lc) * 2;
                ldm_x4(bh[p], bB + off);
                ldm_x4(bl[p], bB + MAT_B + off);
            }
#pragma unroll
            for (int mt = 0; mt < 2; mt++)
#pragma unroll
                for (int nt = 0; nt < 8; nt++) {
                    int p = nt >> 1, h = (nt & 1) * 2;
                    mma_f16(acc[mt][nt], ah[mt], bh[p][h], bh[p][h + 1]);
                    mma_f16(acc[mt][nt], ah[mt], bl[p][h], bl[p][h + 1]);
                }
        }
        cur = (cur + 1 >= 3) ? 0 : cur + 1;
    }

    // ---- epilogue: relu(+lb2), project through L3, RED into out ----
    float pr[4][2];
#pragma unroll
    for (int i = 0; i < 4; i++) { pr[i][0] = 0.f; pr[i][1] = 0.f; }
#pragma unroll
    for (int mt = 0; mt < 2; mt++)
#pragma unroll
        for (int r = 0; r < 2; r++) {
            int idx = mt * 2 + r;
#pragma unroll
            for (int nt = 0; nt < 8; nt++) {
                int n = wn + nt * 8 + (lane & 3) * 2;
                float v0 = fmaxf(acc[mt][nt][r * 2 + 0] + lb2[n0 + n], 0.f);
                float v1 = fmaxf(acc[mt][nt][r * 2 + 1] + lb2[n0 + n + 1], 0.f);
                pr[idx][0] += v0 * sL3[2 * n + 0] + v1 * sL3[2 * (n + 1) + 0];
                pr[idx][1] += v0 * sL3[2 * n + 1] + v1 * sL3[2 * (n + 1) + 1];
            }
        }
#pragma unroll
    for (int i = 0; i < 4; i++) {
#pragma unroll
        for (int o = 1; o < 4; o <<= 1) {
            pr[i][0] += __shfl_xor_sync(0xffffffffu, pr[i][0], o);
            pr[i][1] += __shfl_xor_sync(0xffffffffu, pr[i][1], o);
        }
    }
    if ((lane & 3) == 0) {
#pragma unroll
        for (int mt = 0; mt < 2; mt++)
#pragma unroll
            for (int r = 0; r < 2; r++) {
                int m = m0 + wm + mt * 16 + (lane >> 2) + r * 8;
                if (m < Mreal) {
                    float* dst = outp + (size_t)m * 2;
                    asm volatile("red.global.add.v2.f32 [%0], {%1,%2};"
                                 :: "l"(dst), "f"(pr[mt * 2 + r][0]),
                                    "f"(pr[mt * 2 + r][1]) : "memory");
                }
            }
    }
}

// ---------------------------------------------------------------------------
// FUSED CSR gather (layer 1) + GEMM-n12 (unchanged)
// ---------------------------------------------------------------------------
__global__ void __launch_bounds__(256) k_g128n12(
    const float* __restrict__ b1, const float* __restrict__ W2, int n) {
    __shared__ float sWt[12 * 128];
    for (int i = threadIdx.x; i < 12 * 128; i += 256) {
        int j = i >> 7, k = i & 127;
        sWt[i] = W2[k * 12 + j];
    }
    __syncthreads();
    int w = (blockIdx.x * blockDim.x + threadIdx.x) >> 5;
    int lane = threadIdx.x & 31;
    if (w >= n) return;
    int s = g_rowptr[w], e = g_rowptr[w + 1];
    const float4* base = (const float4*)g_h1s;
    float dw = g_dinv[w];
    float4 acc = base[(size_t)w * 32 + lane];
    acc.x *= dw; acc.y *= dw; acc.z *= dw; acc.w *= dw;
    int i = s;
    for (; i + 3 < e; i += 4) {
        int r0 = __ldg(&g_eidx[i]);
        int r1 = __ldg(&g_eidx[i + 1]);
        int r2 = __ldg(&g_eidx[i + 2]);
        int r3 = __ldg(&g_eidx[i + 3]);
        float d0 = g_dinv[r0], d1 = g_dinv[r1];
        float d2 = g_dinv[r2], d3 = g_dinv[r3];
        float4 v0 = base[(size_t)r0 * 32 + lane];
        float4 v1 = base[(size_t)r1 * 32 + lane];
        float4 v2 = base[(size_t)r2 * 32 + lane];
        float4 v3 = base[(size_t)r3 * 32 + lane];
        acc.x += v0.x * d0 + v1.x * d1 + v2.x * d2 + v3.x * d3;
        acc.y += v0.y * d0 + v1.y * d1 + v2.y * d2 + v3.y * d3;
        acc.z += v0.z * d0 + v1.z * d1 + v2.z * d2 + v3.z * d3;
        acc.w += v0.w * d0 + v1.w * d1 + v2.w * d2 + v3.w * d3;
    }
    for (; i < e; i++) {
        int r = __ldg(&g_eidx[i]);
        float d = g_dinv[r];
        float4 v = base[(size_t)r * 32 + lane];
        acc.x += v.x * d; acc.y += v.y * d;
        acc.z += v.z * d; acc.w += v.w * d;
    }
    float4 bb = ((const float4*)b1)[lane];
    float4 o;
    o.x = fmaxf(acc.x * dw + bb.x, 0.f);
    o.y = fmaxf(acc.y * dw + bb.y, 0.f);
    o.z = fmaxf(acc.z * dw + bb.z, 0.f);
    o.w = fmaxf(acc.w * dw + bb.w, 0.f);

    float p[12];
#pragma unroll
    for (int j = 0; j < 12; j++) {
        float4 wv = *(const float4*)&sWt[j * 128 + lane * 4];
        p[j] = o.x * wv.x + o.y * wv.y + o.z * wv.z + o.w * wv.w;
    }
#pragma unroll
    for (int off = 16; off > 0; off >>= 1)
#pragma unroll
        for (int j = 0; j < 12; j++)
            p[j] += __shfl_xor_sync(0xffffffffu, p[j], off);
#pragma unroll
    for (int j = 0; j < 12; j++)
        if (lane == j) g_h2s[(size_t)w * 12 + j] = p[j] * dw;
}

// ---------------------------------------------------------------------------
// CSR gather, layer 2 (12-dim)
// ---------------------------------------------------------------------------
__global__ void k_gather12(const float* __restrict__ b2, int n) {
    int w = (blockIdx.x * blockDim.x + threadIdx.x) >> 5;
    int lane = threadIdx.x & 31;
    if (w >= n) return;
    int s = g_rowptr[w], e = g_rowptr[w + 1];
    float acc = (lane < 12) ? g_h2s[(size_t)w * 12 + lane] : 0.f;
    for (int i = s; i < e; i++) {
        int r = __ldg(&g_eidx[i]);
        if (lane < 12) acc += g_h2s[(size_t)r * 12 + lane];
    }
    if (lane < 12) {
        float d = g_dinv[w];
        g_h2[(size_t)w * 12 + lane] = fmaxf(acc * d + b2[lane], 0.f);
    }
}

// ---------------------------------------------------------------------------
// Launch
// ---------------------------------------------------------------------------
extern "C" void kernel_launch(void* const* d_in, const int* in_sizes, int n_in,
                              void* d_out, int out_size) {
    const float* x   = (const float*)d_in[0];
    const int*   ei  = (const int*)  d_in[1];
    const float* W1  = (const float*)d_in[2];
    const float* b1  = (const float*)d_in[3];
    const float* W2  = (const float*)d_in[4];
    const float* b2  = (const float*)d_in[5];
    const float* L1  = (const float*)d_in[6];
    const float* lb1 = (const float*)d_in[7];
    const float* L2  = (const float*)d_in[8];
    const float* lb2 = (const float*)d_in[9];
    const float* L3  = (const float*)d_in[10];
    const float* lb3 = (const float*)d_in[11];
    float* out = (float*)d_out;

    const int N = in_sizes[0] / 256;
    const int E = in_sizes[1] / 2;
    const int* row = ei;
    const int* col = ei + E;

    float *p_h1s;
    __nv_bfloat16 *p_w1th, *p_w1tl;
    __half *p_bth, *p_btl, *p_m1h;
    cudaGetSymbolAddress((void**)&p_h1s,  g_h1s);
    cudaGetSymbolAddress((void**)&p_w1th, g_w1th);
    cudaGetSymbolAddress((void**)&p_w1tl, g_w1tl);
    cudaGetSymbolAddress((void**)&p_bth,  g_bth);
    cudaGetSymbolAddress((void**)&p_btl,  g_btl);
    cudaGetSymbolAddress((void**)&p_m1h,  g_m1h);

    cudaFuncSetAttribute(k_mma1f, cudaFuncAttributeMaxDynamicSharedMemorySize, DSM_1F);
    cudaFuncSetAttribute(k_mma2f, cudaFuncAttributeMaxDynamicSharedMemorySize, DSM_G);

    const bool dual = g_si.ok;
    cudaStream_t s2 = dual ? g_si.s2 : (cudaStream_t)0;

    if (dual) {
        cudaEventRecord(g_si.evF, 0);
        cudaStreamWaitEvent(s2, g_si.evF, 0);
    }

    // --- side stream: degrees, dinv, CSR, L2 prep, out init ---
    const int NB = (50000 + 1023) / 1024;
    k_ideg_init <<<(NMAX + 255) / 256, 256, 0, s2>>>();
    k_ideg_edges<<<(E + 255) / 256, 256, 0, s2>>>(col, E);
    k_dinv_calc <<<(NMAX + 255) / 256, 256, 0, s2>>>();
    k_scan1     <<<NB, 1024, 0, s2>>>(N);
    k_scan2     <<<1, 1, 0, s2>>>(NB, N);
    k_scan3     <<<(N + 1023) / 1024, 1024, 0, s2>>>(N);
    k_fill      <<<(E + 255) / 256, 256, 0, s2>>>(row, col, E);
    if (dual) cudaEventRecord(g_si.evC, s2);
    k_bt_prep_h<<<(512 * 512 + 255) / 256, 256, 0, s2>>>(L2, p_bth, p_btl, 512, 512);
    k_out_init <<<(N + 255) / 256, 256, 0, s2>>>(lb3, out, N);
    if (dual) cudaEventRecord(g_si.evP, s2);

    // --- main stream: layer-1 GEMM (independent of CSR chain) ---
    k_bt_prep<<<(128 * 256 + 255) / 256, 256>>>(W1, p_w1th, p_w1tl, 256, 128);
    k_mma1f<<<NMAX / 128, 256, DSM_1F>>>(x, p_w1th, p_w1tl, p_h1s, N);

    if (dual) cudaStreamWaitEvent(0, g_si.evC, 0);
    k_g128n12<<<(N * 32 + 255) / 256, 256>>>(b1, W2, N);
    k_gather12<<<(N * 32 + 255) / 256, 256>>>(b2, N);
    k_mlp1h<<<(N + 63) / 64, 256>>>(L1, lb1, N);

    if (dual) cudaStreamWaitEvent(0, g_si.evP, 0);
    k_mma2f<<<dim3(4, NMAX / 128), 256, DSM_G>>>(
        p_m1h, p_bth, p_btl, lb2, L3, out, N);
}

// round 16
// speedup vs baseline: 1.1670x; 1.1670x over previous
#include <cuda_runtime.h>
#include <cuda_bf16.h>
#include <cuda_fp16.h>
#include <cstdint>

// ---------------------------------------------------------------------------
// Problem constants: N=50000, E=800000, F=256
// ---------------------------------------------------------------------------
#define NMAX 50176   // 50000 rounded up to multiple of 128
#define EMAX 800000

// Scratch (device globals; allocation-free kernel_launch)
__device__ float g_dinv[NMAX];
__device__ int   g_indeg[NMAX];
__device__ int   g_rowptr[NMAX + 1];
__device__ int   g_cursor[NMAX];
__device__ int   g_bsum[64];
__device__ int   g_eidx[EMAX];
__device__ float g_h1s [(size_t)NMAX * 128];          // x@W1 (unscaled)
__device__ float g_h2s [(size_t)NMAX * 12];           // dinv * (out1@W2)
__device__ __half g_m1h[(size_t)NMAX * 512];          // fp16 m1 (rows>=N stay 0)
__device__ __nv_bfloat16 g_w1th[128 * 256];           // bf16 split of W1^T
__device__ __nv_bfloat16 g_w1tl[128 * 256];
__device__ __half g_bth[512 * 512];                   // fp16 split of L2^T
__device__ __half g_btl[512 * 512];

// ---------------------------------------------------------------------------
// Streams/events for fork-join overlap (static-init; fallback to stream 0)
// ---------------------------------------------------------------------------
struct StreamInit {
    cudaStream_t s2 = nullptr;
    cudaEvent_t evF = nullptr, evC = nullptr, evP = nullptr;
    bool ok = false;
    StreamInit() {
        ok = (cudaStreamCreateWithFlags(&s2, cudaStreamNonBlocking) == cudaSuccess)
          && (cudaEventCreateWithFlags(&evF, cudaEventDisableTiming) == cudaSuccess)
          && (cudaEventCreateWithFlags(&evC, cudaEventDisableTiming) == cudaSuccess)
          && (cudaEventCreateWithFlags(&evP, cudaEventDisableTiming) == cudaSuccess);
    }
};
static StreamInit g_si;

// ---------------------------------------------------------------------------
// PTX helpers
// ---------------------------------------------------------------------------
__device__ __forceinline__ uint32_t smem_u32(const void* p) {
    return (uint32_t)__cvta_generic_to_shared(p);
}
__device__ __forceinline__ void ldm_x4(uint32_t* r, uint32_t addr) {
    asm volatile("ldmatrix.sync.aligned.m8n8.x4.shared.b16 {%0,%1,%2,%3}, [%4];"
                 : "=r"(r[0]), "=r"(r[1]), "=r"(r[2]), "=r"(r[3]) : "r"(addr));
}
__device__ __forceinline__ void mma_bf16(float* c, const uint32_t* a,
                                         uint32_t b0, uint32_t b1) {
    asm volatile(
        "mma.sync.aligned.m16n8k16.row.col.f32.bf16.bf16.f32 "
        "{%0,%1,%2,%3}, {%4,%5,%6,%7}, {%8,%9}, {%0,%1,%2,%3};"
        : "+f"(c[0]), "+f"(c[1]), "+f"(c[2]), "+f"(c[3])
        : "r"(a[0]), "r"(a[1]), "r"(a[2]), "r"(a[3]), "r"(b0), "r"(b1));
}
__device__ __forceinline__ void mma_f16(float* c, const uint32_t* a,
                                        uint32_t b0, uint32_t b1) {
    asm volatile(
        "mma.sync.aligned.m16n8k16.row.col.f32.f16.f16.f32 "
        "{%0,%1,%2,%3}, {%4,%5,%6,%7}, {%8,%9}, {%0,%1,%2,%3};"
        : "+f"(c[0]), "+f"(c[1]), "+f"(c[2]), "+f"(c[3])
        : "r"(a[0]), "r"(a[1]), "r"(a[2]), "r"(a[3]), "r"(b0), "r"(b1));
}
#define CP_ASYNC16(dst, src) \
    asm volatile("cp.async.cg.shared.global [%0], [%1], 16;" :: "r"(dst), "l"(src))
#define CP_COMMIT() asm volatile("cp.async.commit_group;" ::: "memory")
#define CP_WAIT1()  asm volatile("cp.async.wait_group 1;" ::: "memory")

__device__ __forceinline__ uint32_t pk_bf2(__nv_bfloat16 a, __nv_bfloat16 b) {
    __nv_bfloat162 t(a, b);
    return *reinterpret_cast<uint32_t*>(&t);
}
__device__ __forceinline__ uint32_t pk_h2(__half a, __half b) {
    __half2 t = __halves2half2(a, b);
    return *reinterpret_cast<uint32_t*>(&t);
}

// ---------------------------------------------------------------------------
// Degree / dinv / CSR build (hierarchical scan)
// ---------------------------------------------------------------------------
__global__ void k_ideg_init() {
    int i = blockIdx.x * blockDim.x + threadIdx.x;
    if (i < NMAX) g_indeg[i] = 0;
}
__global__ void k_ideg_edges(const int* __restrict__ col, int E) {
    int e = blockIdx.x * blockDim.x + threadIdx.x;
    if (e < E) atomicAdd(&g_indeg[col[e]], 1);
}
__global__ void k_dinv_calc() {
    int i = blockIdx.x * blockDim.x + threadIdx.x;
    if (i < NMAX) g_dinv[i] = rsqrtf((float)(g_indeg[i] + 1));
}
__global__ void __launch_bounds__(1024) k_scan1(int n) {
    __shared__ int wsum[32];
    const int tid = threadIdx.x, lane = tid & 31, wid = tid >> 5;
    int i = blockIdx.x * 1024 + tid;
    int v = (i < n) ? g_indeg[i] : 0;
    int s = v;
#pragma unroll
    for (int o = 1; o < 32; o <<= 1) {
        int t = __shfl_up_sync(0xffffffffu, s, o);
        if (lane >= o) s += t;
    }
    if (lane == 31) wsum[wid] = s;
    __syncthreads();
    if (wid == 0) {
        int w = wsum[lane];
#pragma unroll
        for (int o = 1; o < 32; o <<= 1) {
            int t = __shfl_up_sync(0xffffffffu, w, o);
            if (lane >= o) w += t;
        }
        wsum[lane] = w;
    }
    __syncthreads();
    int excl = s - v + (wid ? wsum[wid - 1] : 0);
    if (i < n) g_rowptr[i] = excl;
    if (tid == 1023) g_bsum[blockIdx.x] = wsum[31];
}
__global__ void k_scan2(int nb, int n) {
    int acc = 0;
    for (int b = 0; b < nb; b++) { int t = g_bsum[b]; g_bsum[b] = acc; acc += t; }
    g_rowptr[n] = acc;
}
__global__ void k_scan3(int n) {
    int i = blockIdx.x * blockDim.x + threadIdx.x;
    if (i < n) {
        int v = g_rowptr[i] + g_bsum[i >> 10];
        g_rowptr[i] = v;
        g_cursor[i] = v;
    }
}
__global__ void k_fill(const int* __restrict__ row,
                       const int* __restrict__ col, int E) {
    int e = blockIdx.x * blockDim.x + threadIdx.x;
    if (e >= E) return;
    int p = atomicAdd(&g_cursor[col[e]], 1);
    g_eidx[p] = row[e];
}

// ---------------------------------------------------------------------------
// Transposed-weight prep + output init
// ---------------------------------------------------------------------------
__global__ void k_bt_prep(const float* __restrict__ W,
                          __nv_bfloat16* __restrict__ th,
                          __nv_bfloat16* __restrict__ tl, int K, int N) {
    int i = blockIdx.x * blockDim.x + threadIdx.x;
    if (i >= N * K) return;
    int n = i / K, k = i - n * K;
    float v = W[(size_t)k * N + n];
    __nv_bfloat16 h = __float2bfloat16(v);
    th[i] = h;
    tl[i] = __float2bfloat16(v - __bfloat162float(h));
}
__global__ void k_bt_prep_h(const float* __restrict__ W,
                            __half* __restrict__ th,
                            __half* __restrict__ tl, int K, int N) {
    int i = blockIdx.x * blockDim.x + threadIdx.x;
    if (i >= N * K) return;
    int n = i / K, k = i - n * K;
    float v = W[(size_t)k * N + n];
    __half h = __float2half(v);
    th[i] = h;
    tl[i] = __float2half(v - __half2float(h));
}
__global__ void k_out_init(const float* __restrict__ lb3,
                           float* __restrict__ out, int n) {
    int i = blockIdx.x * blockDim.x + threadIdx.x;
    if (i < n) ((float2*)out)[i] = make_float2(lb3[0], lb3[1]);
}

// ---------------------------------------------------------------------------
// Layer-1 GEMM, fused x-split (bf16 3-term): C[m,n] = x[m,:] @ W1 (unscaled).
// ---------------------------------------------------------------------------
#define SMP 40
#define MAT_B (128 * SMP * 2)    // 10240 B per 128x32 16-bit matrix
#define A1_AH (4 * MAT_B)
#define A1_AL (A1_AH + MAT_B)
#define DSM_1F (A1_AH + 2 * MAT_B)

__global__ void __launch_bounds__(256) k_mma1f(
    const float* __restrict__ x,
    const __nv_bfloat16* __restrict__ BTh, const __nv_bfloat16* __restrict__ BTl,
    float* __restrict__ C, int Nreal)
{
    extern __shared__ char dsm[];
    const uint32_t sb = smem_u32(dsm);
    const int tid = threadIdx.x;
    const int lane = tid & 31;
    const int wid = tid >> 5;
    const int wm = (wid & 3) * 32;
    const int wn = (wid >> 2) * 64;
    const int m0 = blockIdx.x * 128;
    const int K = 256, ntiles = 8, N = 128;

    float acc[2][8][4];
#pragma unroll
    for (int i = 0; i < 2; i++)
#pragma unroll
        for (int j = 0; j < 8; j++)
#pragma unroll
            for (int t = 0; t < 4; t++) acc[i][j][t] = 0.f;

    const int a_lr = lane & 15, a_lc = (lane >> 4) * 8;
    const int b_lr = (lane & 7) + ((lane >> 4) << 3);
    const int b_lc = ((lane >> 3) & 1) * 8;

    auto issueB = [&](int kt, int buf) {
#pragma unroll
        for (int s = tid; s < 512; s += 256) {
            int row = s >> 2, q = s & 3;
            uint32_t so = sb + buf * (2 * MAT_B)
                        + (uint32_t)(row * SMP + q * 8) * 2;
            size_t gb = (size_t)row * K + kt * 32 + q * 8;
            CP_ASYNC16(so,         BTh + gb);
            CP_ASYNC16(so + MAT_B, BTl + gb);
        }
    };

    issueB(0, 0);
    CP_COMMIT();

    const int arow = tid >> 1;
    const int ch = (tid & 1) * 16;
    int gr = m0 + arow;
    if (gr >= Nreal) gr = Nreal - 1;
    const float* xrow = x + (size_t)gr * 256;

    for (int kt = 0; kt < ntiles; kt++) {
        const int cur = kt & 1;
        __syncthreads();
        if (kt + 1 < ntiles) issueB(kt + 1, cur ^ 1);
        CP_COMMIT();

#pragma unroll
        for (int q = 0; q < 4; q++) {
            int col = ch + q * 4;
            float4 s = *(const float4*)(xrow + kt * 32 + col);
            __nv_bfloat16 h0 = __float2bfloat16(s.x);
            __nv_bfloat16 h1 = __float2bfloat16(s.y);
            __nv_bfloat16 h2 = __float2bfloat16(s.z);
            __nv_bfloat16 h3 = __float2bfloat16(s.w);
            uint2 hi = make_uint2(pk_bf2(h0, h1), pk_bf2(h2, h3));
            float l0 = s.x - __bfloat162float(h0);
            float l1 = s.y - __bfloat162float(h1);
            float l2 = s.z - __bfloat162float(h2);
            float l3 = s.w - __bfloat162float(h3);
            uint2 lo = make_uint2(
                pk_bf2(__float2bfloat16(l0), __float2bfloat16(l1)),
                pk_bf2(__float2bfloat16(l2), __float2bfloat16(l3)));
            uint32_t off = (uint32_t)(arow * SMP + col) * 2;
            *(uint2*)(dsm + A1_AH + off) = hi;
            *(uint2*)(dsm + A1_AL + off) = lo;
        }

        CP_WAIT1();
        __syncthreads();

        const uint32_t bA = sb + A1_AH;
        const uint32_t bB = sb + cur * (2 * MAT_B);
#pragma unroll
        for (int ks = 0; ks < 2; ks++) {
            uint32_t ah[2][4], al[2][4], bh[4][4], bl[4][4];
#pragma unroll
            for (int mt = 0; mt < 2; mt++) {
                uint32_t off = (uint32_t)((wm + mt * 16 + a_lr) * SMP
                                          + ks * 16 + a_lc) * 2;
                ldm_x4(ah[mt], bA + off);
                ldm_x4(al[mt], bA + MAT_B + off);
            }
#pragma unroll
            for (int p = 0; p < 4; p++) {
                uint32_t off = (uint32_t)((wn + p * 16 + b_lr) * SMP
                                          + ks * 16 + b_lc) * 2;
                ldm_x4(bh[p], bB + off);
                ldm_x4(bl[p], bB + MAT_B + off);
            }
#pragma unroll
            for (int mt = 0; mt < 2; mt++)
#pragma unroll
                for (int nt = 0; nt < 8; nt++) {
                    int p = nt >> 1, h = (nt & 1) * 2;
                    mma_bf16(acc[mt][nt], ah[mt], bh[p][h], bh[p][h + 1]);
                    mma_bf16(acc[mt][nt], ah[mt], bl[p][h], bl[p][h + 1]);
                    mma_bf16(acc[mt][nt], al[mt], bh[p][h], bh[p][h + 1]);
                }
        }
    }

#pragma unroll
    for (int mt = 0; mt < 2; mt++) {
#pragma unroll
        for (int r = 0; r < 2; r++) {
            int m = m0 + wm + mt * 16 + (lane >> 2) + r * 8;
#pragma unroll
            for (int nt = 0; nt < 8; nt++) {
                int n = wn + nt * 8 + (lane & 3) * 2;
                *(float2*)(C + (size_t)m * N + n)
                    = make_float2(acc[mt][nt][r * 2 + 0],
                                  acc[mt][nt][r * 2 + 1]);
            }
        }
    }
}

// ---------------------------------------------------------------------------
// FUSED gather12 + MLP-1: per node,
//   h2 = relu(dinv*(h2s_self + sum_in h2s[r]) + b2)     (12 dims, in-warp)
//   m1h[node,:] = fp16(relu(h2 @ L1 + lb1))             (512 cols)
// Block = 256 threads (8 warps) x 8 nodes per warp = 64 nodes/block.
// Rows >= n of g_m1h stay 0 (never written; device globals zero-init).
// ---------------------------------------------------------------------------
__global__ void __launch_bounds__(256) k_g12m1(
    const float* __restrict__ b2,
    const float* __restrict__ L1, const float* __restrict__ lb1, int n) {
    __shared__ float sL1[12 * 512];
    __shared__ float sLb1[512];
    __shared__ float sB2[12];
    for (int i = threadIdx.x; i < 12 * 512; i += 256) sL1[i] = L1[i];
    for (int i = threadIdx.x; i < 512; i += 256) sLb1[i] = lb1[i];
    if (threadIdx.x < 12) sB2[threadIdx.x] = b2[threadIdx.x];
    __syncthreads();
    const int wid = threadIdx.x >> 5, lane = threadIdx.x & 31;
    const int node0 = blockIdx.x * 64 + wid * 8;
    for (int t = 0; t < 8; t++) {
        int node = node0 + t;
        if (node >= n) return;
        int s = g_rowptr[node], e = g_rowptr[node + 1];
        float dw = g_dinv[node];
        float acc = (lane < 12) ? g_h2s[(size_t)node * 12 + lane] : 0.f;
        for (int i = s; i < e; i++) {
            int r = __ldg(&g_eidx[i]);
            if (lane < 12) acc += g_h2s[(size_t)r * 12 + lane];
        }
        float h2v = fmaxf(acc * dw + ((lane < 12) ? sB2[lane] : 0.f), 0.f);
        float hv[12];
#pragma unroll
        for (int k = 0; k < 12; k++)
            hv[k] = __shfl_sync(0xffffffffu, h2v, k);
        // each lane: 8 column-pairs j = 2*lane + 64*c (coalesced u32 stores)
#pragma unroll
        for (int c = 0; c < 8; c++) {
            int j = 2 * lane + 64 * c;
            float s0 = sLb1[j], s1 = sLb1[j + 1];
#pragma unroll
            for (int k = 0; k < 12; k++) {
                s0 += hv[k] * sL1[k * 512 + j];
                s1 += hv[k] * sL1[k * 512 + j + 1];
            }
            s0 = fmaxf(s0, 0.f);
            s1 = fmaxf(s1, 0.f);
            *(uint32_t*)(g_m1h + (size_t)node * 512 + j)
                = pk_h2(__float2half(s0), __float2half(s1));
        }
    }
}

// ---------------------------------------------------------------------------
// MLP GEMM, fp16 2-term B-split, 2-stage cp.async pipeline (round-13 form):
//   out[m,:2] += L3^T @ relu( A@(Bh+Bl) + lb2 ),  A = g_m1h
// Grid (Ntiles=4, Mtiles=392): n-tile on x => A m-tile L2-resident.
// ---------------------------------------------------------------------------
#define G_STG (3 * MAT_B)                      // A,Bh,Bl per stage: 30720
#define G_L3  (2 * G_STG)                      // 61440
#define DSM_G (G_L3 + 128 * 2 * 4)             // 62464

__global__ void __launch_bounds__(256) k_mma2f(
    const __half* __restrict__ Ah,
    const __half* __restrict__ BTh, const __half* __restrict__ BTl,
    const float* __restrict__ lb2,
    const float* __restrict__ L3, float* __restrict__ outp, int Mreal)
{
    extern __shared__ char dsm[];
    const uint32_t sb = smem_u32(dsm);
    float* sL3 = (float*)(dsm + G_L3);

    const int tid = threadIdx.x;
    const int lane = tid & 31;
    const int wid = tid >> 5;
    const int wm = (wid & 3) * 32;
    const int wn = (wid >> 2) * 64;
    const int m0 = blockIdx.y * 128;
    const int n0 = blockIdx.x * 128;
    const int K = 512, ntiles = 16;

    if (tid < 128) ((float2*)sL3)[tid] = ((const float2*)L3)[n0 + tid];

    float acc[2][8][4];
#pragma unroll
    for (int i = 0; i < 2; i++)
#pragma unroll
        for (int j = 0; j < 8; j++)
#pragma unroll
            for (int t = 0; t < 4; t++) acc[i][j][t] = 0.f;

    const int a_lr = lane & 15, a_lc = (lane >> 4) * 8;
    const int b_lr = (lane & 7) + ((lane >> 4) << 3);
    const int b_lc = ((lane >> 3) & 1) * 8;

    auto issue = [&](int kt, int buf) {
        const uint32_t bb = sb + buf * G_STG;
#pragma unroll
        for (int s = tid; s < 512; s += 256) {
            int row = s >> 2, q = s & 3;
            uint32_t so = (uint32_t)(row * SMP + q * 8) * 2;
            size_t ga = (size_t)(m0 + row) * K + kt * 32 + q * 8;
            size_t gb = (size_t)(n0 + row) * K + kt * 32 + q * 8;
            CP_ASYNC16(bb + so,             Ah + ga);
            CP_ASYNC16(bb + MAT_B + so,     BTh + gb);
            CP_ASYNC16(bb + 2 * MAT_B + so, BTl + gb);
        }
    };

    issue(0, 0);
    CP_COMMIT();

    for (int kt = 0; kt < ntiles; kt++) {
        const int cur = kt & 1;
        if (kt + 1 < ntiles) issue(kt + 1, cur ^ 1);
        CP_COMMIT();
        CP_WAIT1();
        __syncthreads();

        const uint32_t bA = sb + cur * G_STG;
        const uint32_t bB = bA + MAT_B;
#pragma unroll
        for (int ks = 0; ks < 2; ks++) {
            uint32_t ah[2][4], bh[4][4], bl[4][4];
#pragma unroll
            for (int mt = 0; mt < 2; mt++) {
                uint32_t off = (uint32_t)((wm + mt * 16 + a_lr) * SMP
                                          + ks * 16 + a_lc) * 2;
                ldm_x4(ah[mt], bA + off);
            }
#pragma unroll
            for (int p = 0; p < 4; p++) {
                uint32_t off = (uint32_t)((wn + p * 16 + b_lr) * SMP
                                          + ks * 16 + b_lc) * 2;
                ldm_x4(bh[p], bB + off);
                ldm_x4(bl[p], bB + MAT_B + off);
            }
#pragma unroll
            for (int mt = 0; mt < 2; mt++)
#pragma unroll
                for (int nt = 0; nt < 8; nt++) {
                    int p = nt >> 1, h = (nt & 1) * 2;
                    mma_f16(acc[mt][nt], ah[mt], bh[p][h], bh[p][h + 1]);
                    mma_f16(acc[mt][nt], ah[mt], bl[p][h], bl[p][h + 1]);
                }
        }
        __syncthreads();
    }

    // ---- epilogue: relu(+lb2), project through L3, RED into out ----
    float pr[4][2];
#pragma unroll
    for (int i = 0; i < 4; i++) { pr[i][0] = 0.f; pr[i][1] = 0.f; }
#pragma unroll
    for (int mt = 0; mt < 2; mt++)
#pragma unroll
        for (int r = 0; r < 2; r++) {
            int idx = mt * 2 + r;
#pragma unroll
            for (int nt = 0; nt < 8; nt++) {
                int n = wn + nt * 8 + (lane & 3) * 2;
                float v0 = fmaxf(acc[mt][nt][r * 2 + 0] + lb2[n0 + n], 0.f);
                float v1 = fmaxf(acc[mt][nt][r * 2 + 1] + lb2[n0 + n + 1], 0.f);
                pr[idx][0] += v0 * sL3[2 * n + 0] + v1 * sL3[2 * (n + 1) + 0];
                pr[idx][1] += v0 * sL3[2 * n + 1] + v1 * sL3[2 * (n + 1) + 1];
            }
        }
#pragma unroll
    for (int i = 0; i < 4; i++) {
#pragma unroll
        for (int o = 1; o < 4; o <<= 1) {
            pr[i][0] += __shfl_xor_sync(0xffffffffu, pr[i][0], o);
            pr[i][1] += __shfl_xor_sync(0xffffffffu, pr[i][1], o);
        }
    }
    if ((lane & 3) == 0) {
#pragma unroll
        for (int mt = 0; mt < 2; mt++)
#pragma unroll
            for (int r = 0; r < 2; r++) {
                int m = m0 + wm + mt * 16 + (lane >> 2) + r * 8;
                if (m < Mreal) {
                    float* dst = outp + (size_t)m * 2;
                    asm volatile("red.global.add.v2.f32 [%0], {%1,%2};"
                                 :: "l"(dst), "f"(pr[mt * 2 + r][0]),
                                    "f"(pr[mt * 2 + r][1]) : "memory");
                }
            }
    }
}

// ---------------------------------------------------------------------------
// FUSED CSR gather (layer 1) + GEMM-n12 (unchanged)
// ---------------------------------------------------------------------------
__global__ void __launch_bounds__(256) k_g128n12(
    const float* __restrict__ b1, const float* __restrict__ W2, int n) {
    __shared__ float sWt[12 * 128];
    for (int i = threadIdx.x; i < 12 * 128; i += 256) {
        int j = i >> 7, k = i & 127;
        sWt[i] = W2[k * 12 + j];
    }
    __syncthreads();
    int w = (blockIdx.x * blockDim.x + threadIdx.x) >> 5;
    int lane = threadIdx.x & 31;
    if (w >= n) return;
    int s = g_rowptr[w], e = g_rowptr[w + 1];
    const float4* base = (const float4*)g_h1s;
    float dw = g_dinv[w];
    float4 acc = base[(size_t)w * 32 + lane];
    acc.x *= dw; acc.y *= dw; acc.z *= dw; acc.w *= dw;
    int i = s;
    for (; i + 3 < e; i += 4) {
        int r0 = __ldg(&g_eidx[i]);
        int r1 = __ldg(&g_eidx[i + 1]);
        int r2 = __ldg(&g_eidx[i + 2]);
        int r3 = __ldg(&g_eidx[i + 3]);
        float d0 = g_dinv[r0], d1 = g_dinv[r1];
        float d2 = g_dinv[r2], d3 = g_dinv[r3];
        float4 v0 = base[(size_t)r0 * 32 + lane];
        float4 v1 = base[(size_t)r1 * 32 + lane];
        float4 v2 = base[(size_t)r2 * 32 + lane];
        float4 v3 = base[(size_t)r3 * 32 + lane];
        acc.x += v0.x * d0 + v1.x * d1 + v2.x * d2 + v3.x * d3;
        acc.y += v0.y * d0 + v1.y * d1 + v2.y * d2 + v3.y * d3;
        acc.z += v0.z * d0 + v1.z * d1 + v2.z * d2 + v3.z * d3;
        acc.w += v0.w * d0 + v1.w * d1 + v2.w * d2 + v3.w * d3;
    }
    for (; i < e; i++) {
        int r = __ldg(&g_eidx[i]);
        float d = g_dinv[r];
        float4 v = base[(size_t)r * 32 + lane];
        acc.x += v.x * d; acc.y += v.y * d;
        acc.z += v.z * d; acc.w += v.w * d;
    }
    float4 bb = ((const float4*)b1)[lane];
    float4 o;
    o.x = fmaxf(acc.x * dw + bb.x, 0.f);
    o.y = fmaxf(acc.y * dw + bb.y, 0.f);
    o.z = fmaxf(acc.z * dw + bb.z, 0.f);
    o.w = fmaxf(acc.w * dw + bb.w, 0.f);

    float p[12];
#pragma unroll
    for (int j = 0; j < 12; j++) {
        float4 wv = *(const float4*)&sWt[j * 128 + lane * 4];
        p[j] = o.x * wv.x + o.y * wv.y + o.z * wv.z + o.w * wv.w;
    }
#pragma unroll
    for (int off = 16; off > 0; off >>= 1)
#pragma unroll
        for (int j = 0; j < 12; j++)
            p[j] += __shfl_xor_sync(0xffffffffu, p[j], off);
#pragma unroll
    for (int j = 0; j < 12; j++)
        if (lane == j) g_h2s[(size_t)w * 12 + j] = p[j] * dw;
}

// ---------------------------------------------------------------------------
// Launch
// ---------------------------------------------------------------------------
extern "C" void kernel_launch(void* const* d_in, const int* in_sizes, int n_in,
                              void* d_out, int out_size) {
    const float* x   = (const float*)d_in[0];
    const int*   ei  = (const int*)  d_in[1];
    const float* W1  = (const float*)d_in[2];
    const float* b1  = (const float*)d_in[3];
    const float* W2  = (const float*)d_in[4];
    const float* b2  = (const float*)d_in[5];
    const float* L1  = (const float*)d_in[6];
    const float* lb1 = (const float*)d_in[7];
    const float* L2  = (const float*)d_in[8];
    const float* lb2 = (const float*)d_in[9];
    const float* L3  = (const float*)d_in[10];
    const float* lb3 = (const float*)d_in[11];
    float* out = (float*)d_out;

    const int N = in_sizes[0] / 256;
    const int E = in_sizes[1] / 2;
    const int* row = ei;
    const int* col = ei + E;

    float *p_h1s;
    __nv_bfloat16 *p_w1th, *p_w1tl;
    __half *p_bth, *p_btl, *p_m1h;
    cudaGetSymbolAddress((void**)&p_h1s,  g_h1s);
    cudaGetSymbolAddress((void**)&p_w1th, g_w1th);
    cudaGetSymbolAddress((void**)&p_w1tl, g_w1tl);
    cudaGetSymbolAddress((void**)&p_bth,  g_bth);
    cudaGetSymbolAddress((void**)&p_btl,  g_btl);
    cudaGetSymbolAddress((void**)&p_m1h,  g_m1h);

    cudaFuncSetAttribute(k_mma1f, cudaFuncAttributeMaxDynamicSharedMemorySize, DSM_1F);
    cudaFuncSetAttribute(k_mma2f, cudaFuncAttributeMaxDynamicSharedMemorySize, DSM_G);

    const bool dual = g_si.ok;
    cudaStream_t s2 = dual ? g_si.s2 : (cudaStream_t)0;

    if (dual) {
        cudaEventRecord(g_si.evF, 0);
        cudaStreamWaitEvent(s2, g_si.evF, 0);
    }

    // --- side stream: degrees, dinv, CSR, L2 prep, out init ---
    const int NB = (50000 + 1023) / 1024;
    k_ideg_init <<<(NMAX + 255) / 256, 256, 0, s2>>>();
    k_ideg_edges<<<(E + 255) / 256, 256, 0, s2>>>(col, E);
    k_dinv_calc <<<(NMAX + 255) / 256, 256, 0, s2>>>();
    k_scan1     <<<NB, 1024, 0, s2>>>(N);
    k_scan2     <<<1, 1, 0, s2>>>(NB, N);
    k_scan3     <<<(N + 1023) / 1024, 1024, 0, s2>>>(N);
    k_fill      <<<(E + 255) / 256, 256, 0, s2>>>(row, col, E);
    if (dual) cudaEventRecord(g_si.evC, s2);
    k_bt_prep_h<<<(512 * 512 + 255) / 256, 256, 0, s2>>>(L2, p_bth, p_btl, 512, 512);
    k_out_init <<<(N + 255) / 256, 256, 0, s2>>>(lb3, out, N);
    if (dual) cudaEventRecord(g_si.evP, s2);

    // --- main stream: layer-1 GEMM (independent of CSR chain) ---
    k_bt_prep<<<(128 * 256 + 255) / 256, 256>>>(W1, p_w1th, p_w1tl, 256, 128);
    k_mma1f<<<NMAX / 128, 256, DSM_1F>>>(x, p_w1th, p_w1tl, p_h1s, N);

    if (dual) cudaStreamWaitEvent(0, g_si.evC, 0);
    k_g128n12<<<(N * 32 + 255) / 256, 256>>>(b1, W2, N);
    k_g12m1<<<(N + 63) / 64, 256>>>(b2, L1, lb1, N);

    if (dual) cudaStreamWaitEvent(0, g_si.evP, 0);
    k_mma2f<<<dim3(4, NMAX / 128), 256, DSM_G>>>(
        p_m1h, p_bth, p_btl, lb2, L3, out, N);
}